// round 15
// baseline (speedup 1.0000x reference)
#include <cuda_runtime.h>
#include <cuda_bf16.h>
#include <cstdint>

#define LAMBDA_COORD 5.0f
#define LAMBDA_NOOBJ 0.5f
#define EPS 1e-9f
#define WPB 8                   // warps per block (256 threads)
#define BPSM 4                  // blocks per SM (reg cap 64)
#define NBLK (148 * BPSM)       // one resident wave = 592 blocks

__device__ double g_partial[NBLK];
__device__ unsigned g_count = 0;

__device__ __forceinline__ float bbox_iou(float px, float py, float pr,
                                          float gx, float gy, float gr) {
    float l1 = px - pr, r1 = px + pr, t1 = py - pr, b1 = py + pr;
    float l2 = gx - gr, r2 = gx + gr, t2 = gy - gr, b2 = gy + gr;
    float iw = fmaxf(fminf(r1, r2) - fmaxf(l1, l2), 0.0f);
    float ih = fmaxf(fminf(b1, b2) - fmaxf(t1, t2), 0.0f);
    float inter = iw * ih;
    float a1 = (r1 - l1) * (b1 - t1);
    float a2 = (r2 - l2) * (b2 - t2);
    return __fdividef(inter, a1 + a2 - inter + EPS);
}

__global__ void __launch_bounds__(WPB * 32, BPSM)
yolo_loss_kernel(const float* __restrict__ pred,
                 const int*   __restrict__ label_rc,
                 const float* __restrict__ label_box,
                 int B, float* __restrict__ out) {
    __shared__ double blocksum[WPB];
    __shared__ int islast;

    const int warp = threadIdx.x >> 5;
    const int lane = threadIdx.x & 31;
    const int TW = NBLK * WPB;           // total warps = 4736
    const int P = (B + 1) >> 1;          // batch pairs
    const int p0 = blockIdx.x * WPB + warp;

    const int li   = lane & 15;          // label index within batch
    const int half = lane >> 4;          // 0 = batch A, 1 = batch B

    float acc  = 0.0f;   // coord + conf (weighted)
    float nsum = 0.0f;   // c3^2+c7^2 over ALL cells
    float nsub = 0.0f;   // over distinct object cells

    // label-prefetch pipeline state (distance 1)
    int2  nrc = make_int2(0, 0);
    float ngx = 0.f, ngy = 0.f, ngr = 0.f;
    bool  nval = false;

    // issue the 8 stride-16B ".w" loads for pair pp into set w[8].
    // offsets 12+16k touch every 32B sector -> L1 pulls the full slab.
    auto issue_w = [&](float (&w)[8], int pp) {
#pragma unroll
        for (int k = 0; k < 8; k++) w[k] = 0.f;
        if (pp < P) {
            const float* pw = pred + (size_t)pp * 1024 + 3 + 4 * lane;
            w[0] = pw[0];   w[1] = pw[128]; w[2] = pw[256]; w[3] = pw[384];
            if (2 * pp + 1 < B) {
                w[4] = pw[512]; w[5] = pw[640]; w[6] = pw[768]; w[7] = pw[896];
            }
        }
    };

    auto fetch_labels = [&](int pp) {
        nval = false;
        if (pp < P) {
            int bb = 2 * pp + half;
            if (bb < B) {
                nval = true;
                nrc = reinterpret_cast<const int2*>(label_rc)[(size_t)bb * 16 + li];
                const float* bx = label_box + ((size_t)bb * 16 + li) * 3;
                ngx = bx[0]; ngy = bx[1]; ngr = bx[2];
            }
        }
    };

    // consume set w (issued one iteration ago) for pair pv; refill for pv+2*TW
    auto process = [&](float (&w)[8], int pv) {
        // noobj totals — loads already returned, no stall
#pragma unroll
        for (int k = 0; k < 8; k++) nsum = fmaf(w[k], w[k], nsum);

        int2 rc = nrc;
        float gx = ngx, gy = ngy, gr = ngr;
        bool valid = nval;

        // gather this label's cell — lines already resident in L1
        int cell = valid ? (rc.x * 8 + rc.y) : 0;
        int bb = 2 * pv + half;
        if (bb >= B) bb = 2 * pv;
        const float4* cellp = reinterpret_cast<const float4*>(
                                  pred + (size_t)bb * 512) + cell * 2;
        float4 A = cellp[0];
        float4 C = cellp[1];

        // refill stream set (depth-2) + prefetch next labels
        issue_w(w, pv + 2 * TW);
        fetch_labels(pv + TW);

        // dedupe object cells across the pair
        int enc = valid ? (cell + (half << 6)) : (128 + lane);
        unsigned peers = __match_any_sync(0xffffffffu, enc);
        bool leader = (lane == (__ffs(peers) - 1));

        float iou1 = bbox_iou(A.x, A.y, A.z, gx, gy, gr);
        float iou2 = bbox_iou(C.x, C.y, C.z, gx, gy, gr);
        bool swp = iou2 > iou1;

        float cx   = swp ? C.x : A.x;
        float cy   = swp ? C.y : A.y;
        float cr   = swp ? C.z : A.z;
        float conf = swp ? C.w : A.w;
        float ucnf = swp ? A.w : C.w;
        float big  = swp ? iou2 : iou1;
        float sml  = swp ? iou1 : iou2;

        if (valid) {
            float dx = cx - gx, dy = cy - gy, dr = cr - gr;
            acc += LAMBDA_COORD * (dx * dx + dy * dy + dr * dr);
            float dc = big - conf;
            acc += dc * dc;
            float du = sml - ucnf;
            acc += LAMBDA_NOOBJ * du * du;
            if (leader) {
                nsub = fmaf(A.w, A.w, nsub);
                nsub = fmaf(C.w, C.w, nsub);
            }
        }
    };

    // prologue: two stream sets in flight + first pair's labels
    float wa[8], wb[8];
    issue_w(wa, p0);
    issue_w(wb, p0 + TW);
    fetch_labels(p0);

    int p = p0;
    while (p < P) {
        process(wa, p);
        p += TW;
        if (p >= P) break;
        process(wb, p);
        p += TW;
    }

    acc += LAMBDA_NOOBJ * (nsum - nsub);

    // ---- warp reduce -> block reduce ----
#pragma unroll
    for (int o = 16; o > 0; o >>= 1)
        acc += __shfl_xor_sync(0xffffffffu, acc, o);
    if (lane == 0) blocksum[warp] = (double)acc;
    __syncthreads();

    if (threadIdx.x == 0) {
        double s = 0.0;
#pragma unroll
        for (int w = 0; w < WPB; w++) s += blocksum[w];
        g_partial[blockIdx.x] = s;
        __threadfence();
        unsigned ticket = atomicAdd(&g_count, 1u);
        islast = (ticket == (unsigned)(gridDim.x - 1)) ? 1 : 0;
    }
    __syncthreads();

    // ---- last block folds partials (deterministic fixed order) ----
    if (islast) {
        double s = 0.0;
        for (int i = threadIdx.x; i < NBLK; i += WPB * 32)
            s += *((volatile double*)&g_partial[i]);
#pragma unroll
        for (int o = 16; o > 0; o >>= 1)
            s += __shfl_xor_sync(0xffffffffu, s, o);
        __syncthreads();
        if (lane == 0) blocksum[warp] = s;
        __syncthreads();
        if (threadIdx.x == 0) {
            double t = 0.0;
#pragma unroll
            for (int w = 0; w < WPB; w++) t += blocksum[w];
            out[0] = (float)(t / (double)B);
            g_count = 0;  // reset for next graph replay
        }
    }
}

extern "C" void kernel_launch(void* const* d_in, const int* in_sizes, int n_in,
                              void* d_out, int out_size) {
    const float* pred      = (const float*)d_in[0];
    const int*   label_rc  = (const int*)d_in[1];
    const float* label_box = (const float*)d_in[2];
    float* out = (float*)d_out;

    int B = in_sizes[0] / 512;  // pred is [B, 8, 8, 8]

    yolo_loss_kernel<<<NBLK, WPB * 32>>>(pred, label_rc, label_box, B, out);
}

// round 16
// speedup vs baseline: 1.0676x; 1.0676x over previous
#include <cuda_runtime.h>
#include <cuda_bf16.h>
#include <cstdint>

#define LAMBDA_COORD 5.0f
#define LAMBDA_NOOBJ 0.5f
#define EPS 1e-9f
#define WPB 8                   // warps per block (256 threads)
#define BPSM 6                  // blocks per SM (reg cap 42)
#define NBLK (148 * BPSM)       // one resident wave = 888 blocks

__device__ double g_partial[NBLK];
__device__ unsigned g_count = 0;

__device__ __forceinline__ float bbox_iou(float px, float py, float pr,
                                          float gx, float gy, float gr) {
    float l1 = px - pr, r1 = px + pr, t1 = py - pr, b1 = py + pr;
    float l2 = gx - gr, r2 = gx + gr, t2 = gy - gr, b2 = gy + gr;
    float iw = fmaxf(fminf(r1, r2) - fmaxf(l1, l2), 0.0f);
    float ih = fmaxf(fminf(b1, b2) - fmaxf(t1, t2), 0.0f);
    float inter = iw * ih;
    float a1 = (r1 - l1) * (b1 - t1);
    float a2 = (r2 - l2) * (b2 - t2);
    return __fdividef(inter, a1 + a2 - inter + EPS);
}

__global__ void __launch_bounds__(WPB * 32, BPSM)
yolo_loss_kernel(const float* __restrict__ pred,
                 const int*   __restrict__ label_rc,
                 const float* __restrict__ label_box,
                 int B, float* __restrict__ out) {
    __shared__ double blocksum[WPB];
    __shared__ int islast;

    const int warp = threadIdx.x >> 5;
    const int lane = threadIdx.x & 31;
    const int TW = NBLK * WPB;           // total warps = 7104
    const int P = (B + 1) >> 1;          // batch pairs
    const int p0 = blockIdx.x * WPB + warp;

    const int li   = lane & 15;          // label index within batch
    const int half = lane >> 4;          // 0 = batch A, 1 = batch B

    float acc  = 0.0f;   // coord + conf (weighted)
    float nsum = 0.0f;   // c3^2+c7^2 over ALL cells
    float nsub = 0.0f;   // over distinct object cells

    // ---- label prefetch for first pair (distance-1 pipeline) ----
    int2 nrc = make_int2(0, 0);
    float ngx = 0.f, ngy = 0.f, ngr = 0.f;
    bool nval = false;
    if (p0 < P) {
        int bb = 2 * p0 + half;
        if (bb < B) {
            nval = true;
            nrc = reinterpret_cast<const int2*>(label_rc)[(size_t)bb * 16 + li];
            const float* bx = label_box + ((size_t)bb * 16 + li) * 3;
            ngx = bx[0]; ngy = bx[1]; ngr = bx[2];
        }
    }

    for (int p = p0; p < P; p += TW) {
        // ---- stream ONLY the .w words (ch3/ch7) of the 4KB pair.
        //      offsets 12+16k touch every 32B sector -> L1 pulls the whole
        //      slab from DRAM; the gather below MSHR-merges with these.
        const float* pw = pred + (size_t)p * 1024 + 3 + 4 * lane;
        const bool fullpair = (2 * p + 1 < B);
        float w0 = pw[0];
        float w1 = pw[128];
        float w2 = pw[256];
        float w3 = pw[384];
        float w4 = 0.f, w5 = 0.f, w6 = 0.f, w7 = 0.f;
        if (fullpair) {
            w4 = pw[512];
            w5 = pw[640];
            w6 = pw[768];
            w7 = pw[896];
        }

        // ---- current labels (prefetched) ----
        int2 rc = nrc;
        float gx = ngx, gy = ngy, gr = ngr;
        bool valid = nval;

        // ---- gather this label's cell from gmem (sectors just requested;
        //      MSHR merges -> shared DRAM latency) ----
        int cell = valid ? (rc.x * 8 + rc.y) : 0;
        int bb = 2 * p + half;
        if (bb >= B) bb = 2 * p;   // safe address for invalid lanes
        const float4* cellp = reinterpret_cast<const float4*>(
                                  pred + (size_t)bb * 512) + cell * 2;
        float4 A = cellp[0];   // p0..p3
        float4 C = cellp[1];   // q4..q7

        // ---- prefetch next pair's labels ----
        nval = false;
        {
            int pn = p + TW;
            if (pn < P) {
                int nbb = 2 * pn + half;
                if (nbb < B) {
                    nval = true;
                    nrc = reinterpret_cast<const int2*>(label_rc)[(size_t)nbb * 16 + li];
                    const float* bx = label_box + ((size_t)nbb * 16 + li) * 3;
                    ngx = bx[0]; ngy = bx[1]; ngr = bx[2];
                }
            }
        }

        // ---- dedupe object cells across the pair ----
        int enc = valid ? (cell + (half << 6)) : (128 + lane);
        unsigned peers = __match_any_sync(0xffffffffu, enc);
        bool leader = (lane == (__ffs(peers) - 1));

        // ---- noobj total: unconditional FMAs on the streamed .w values ----
        nsum = fmaf(w0, w0, nsum);
        nsum = fmaf(w1, w1, nsum);
        nsum = fmaf(w2, w2, nsum);
        nsum = fmaf(w3, w3, nsum);
        nsum = fmaf(w4, w4, nsum);
        nsum = fmaf(w5, w5, nsum);
        nsum = fmaf(w6, w6, nsum);
        nsum = fmaf(w7, w7, nsum);

        // ---- coord + conf losses (full warp: A-batch lanes 0-15, B 16-31) ----
        float iou1 = bbox_iou(A.x, A.y, A.z, gx, gy, gr);
        float iou2 = bbox_iou(C.x, C.y, C.z, gx, gy, gr);
        bool swp = iou2 > iou1;

        float cx   = swp ? C.x : A.x;
        float cy   = swp ? C.y : A.y;
        float cr   = swp ? C.z : A.z;
        float conf = swp ? C.w : A.w;
        float ucnf = swp ? A.w : C.w;
        float big  = swp ? iou2 : iou1;
        float sml  = swp ? iou1 : iou2;

        if (valid) {
            float dx = cx - gx, dy = cy - gy, dr = cr - gr;
            acc += LAMBDA_COORD * (dx * dx + dy * dy + dr * dr);
            float dc = big - conf;
            acc += dc * dc;
            float du = sml - ucnf;
            acc += LAMBDA_NOOBJ * du * du;
            if (leader) {       // distinct object cell: remove from noobj total
                nsub = fmaf(A.w, A.w, nsub);
                nsub = fmaf(C.w, C.w, nsub);
            }
        }
    }

    acc += LAMBDA_NOOBJ * (nsum - nsub);

    // ---- warp reduce -> block reduce ----
#pragma unroll
    for (int o = 16; o > 0; o >>= 1)
        acc += __shfl_xor_sync(0xffffffffu, acc, o);
    if (lane == 0) blocksum[warp] = (double)acc;
    __syncthreads();

    if (threadIdx.x == 0) {
        double s = 0.0;
#pragma unroll
        for (int w = 0; w < WPB; w++) s += blocksum[w];
        g_partial[blockIdx.x] = s;
        __threadfence();
        unsigned ticket = atomicAdd(&g_count, 1u);
        islast = (ticket == (unsigned)(gridDim.x - 1)) ? 1 : 0;
    }
    __syncthreads();

    // ---- last block folds partials (deterministic fixed order) ----
    if (islast) {
        double s = 0.0;
        for (int i = threadIdx.x; i < NBLK; i += WPB * 32)
            s += *((volatile double*)&g_partial[i]);
#pragma unroll
        for (int o = 16; o > 0; o >>= 1)
            s += __shfl_xor_sync(0xffffffffu, s, o);
        __syncthreads();   // blocksum reusable now
        if (lane == 0) blocksum[warp] = s;
        __syncthreads();
        if (threadIdx.x == 0) {
            double t = 0.0;
#pragma unroll
            for (int w = 0; w < WPB; w++) t += blocksum[w];
            out[0] = (float)(t / (double)B);
            g_count = 0;  // reset for next graph replay
        }
    }
}

extern "C" void kernel_launch(void* const* d_in, const int* in_sizes, int n_in,
                              void* d_out, int out_size) {
    const float* pred      = (const float*)d_in[0];
    const int*   label_rc  = (const int*)d_in[1];
    const float* label_box = (const float*)d_in[2];
    float* out = (float*)d_out;

    int B = in_sizes[0] / 512;  // pred is [B, 8, 8, 8]

    yolo_loss_kernel<<<NBLK, WPB * 32>>>(pred, label_rc, label_box, B, out);
}